// round 2
// baseline (speedup 1.0000x reference)
#include <cuda_runtime.h>
#include <cuda_bf16.h>

#define EPS 1e-9f

static constexpr int BMAX = 1024;
static constexpr int DMAX = 512;
static constexpr int UMAX = 512;

// Scratch (device globals — no allocation allowed)
__device__ float2 g_LN[BMAX * DMAX];   // {log2|x+eps|, neg?1:0}
__device__ float  g_DW[DMAX * UMAX];   // odd(p) ? -2w : 0   (so w + flag*dw = signed w)

// ---------------- Fused prepass ----------------
__global__ void prep_kernel(const float* __restrict__ x,
                            const float* __restrict__ w,
                            const float* __restrict__ p,
                            int nLN, int nDW) {
    int i = blockIdx.x * blockDim.x + threadIdx.x;
    if (i < nLN) {
        float xe = x[i] + EPS;
        g_LN[i] = make_float2(log2f(fabsf(xe)), (xe < 0.f) ? 1.f : 0.f);
    }
    if (i < nDW) {
        float pv = p[i];
        // odd(p) per jnp.mod semantics: nonzero remainder iff p not an even integer
        g_DW[i] = (fmodf(pv, 2.f) != 0.f) ? (-2.f * w[i]) : 0.f;
    }
}

// ---------------- Main kernel ----------------
// 64 threads; each thread owns 2 ADJACENT u-cols (float2 loads) and TBT=8 b-rows.
static constexpr int DC      = 8;
static constexpr int TBT     = 8;
static constexpr int THREADS = 64;

__global__ __launch_bounds__(THREADS)
void power_layer_kernel(const float* __restrict__ w,
                        const float* __restrict__ p,
                        const float* __restrict__ bias,
                        float* __restrict__ out,
                        int D, int U) {
    const int u0 = blockIdx.x * (2 * THREADS) + threadIdx.x * 2;
    const int b0 = blockIdx.y * TBT;
    const int U2 = U >> 1;
    const int uh = u0 >> 1;

    const float2* __restrict__ w2  = (const float2*)w;
    const float2* __restrict__ p2  = (const float2*)p;
    const float2* __restrict__ dw2 = (const float2*)g_DW;

    float2 acc[TBT];
#pragma unroll
    for (int bb = 0; bb < TBT; bb++) acc[bb] = make_float2(0.f, 0.f);

    for (int d0 = 0; d0 < D; d0 += DC) {
        float2 pr[DC], wr[DC], dwr[DC];
#pragma unroll
        for (int j = 0; j < DC; j++) {
            int r = (d0 + j) * U2 + uh;
            pr[j]  = p2[r];
            wr[j]  = w2[r];
            dwr[j] = dw2[r];
        }

#pragma unroll
        for (int bb = 0; bb < TBT; bb++) {
            // warp-uniform ln loads -> L1 broadcast; float4 = 2 x {log2, flag}
            const float4* __restrict__ ln4 =
                (const float4*)(g_LN + (size_t)(b0 + bb) * D + d0);
            float4 lnv[DC / 2];
#pragma unroll
            for (int q = 0; q < DC / 2; q++) lnv[q] = ln4[q];

#pragma unroll
            for (int j = 0; j < DC; j++) {
                const float lv = (j & 1) ? lnv[j >> 1].z : lnv[j >> 1].x;
                const float fl = (j & 1) ? lnv[j >> 1].w : lnv[j >> 1].y;

                float e0 = pr[j].x * lv;
                float e1 = pr[j].y * lv;
                float v0, v1;
                asm("ex2.approx.f32 %0, %1;" : "=f"(v0) : "f"(e0));
                asm("ex2.approx.f32 %0, %1;" : "=f"(v1) : "f"(e1));

                float ws0 = fmaf(fl, dwr[j].x, wr[j].x);   // signed weight
                float ws1 = fmaf(fl, dwr[j].y, wr[j].y);

                acc[bb].x = fmaf(ws0, v0, acc[bb].x);
                acc[bb].y = fmaf(ws1, v1, acc[bb].y);
            }
        }
    }

    const float2 bv = *(const float2*)(bias + u0);
#pragma unroll
    for (int bb = 0; bb < TBT; bb++) {
        float2 o = make_float2(acc[bb].x + bv.x, acc[bb].y + bv.y);
        *(float2*)(out + (size_t)(b0 + bb) * U + u0) = o;
    }
}

// ---------------- Launch ----------------
extern "C" void kernel_launch(void* const* d_in, const int* in_sizes, int n_in,
                              void* d_out, int out_size) {
    const float* x    = (const float*)d_in[0];
    const float* w    = (const float*)d_in[1];
    const float* p    = (const float*)d_in[2];
    const float* bias = (const float*)d_in[3];
    float* out        = (float*)d_out;

    const int U = in_sizes[3];            // 512
    const int D = in_sizes[1] / U;        // 512
    const int B = in_sizes[0] / D;        // 1024

    const int nLN = B * D;                // 524288
    const int nDW = D * U;                // 262144
    const int nmax = nLN > nDW ? nLN : nDW;
    prep_kernel<<<(nmax + 255) / 256, 256>>>(x, w, p, nLN, nDW);

    dim3 grid(U / (2 * THREADS), B / TBT);   // (4, 128) = 512 blocks
    power_layer_kernel<<<grid, THREADS>>>(w, p, bias, out, D, U);
}

// round 3
// speedup vs baseline: 1.2981x; 1.2981x over previous
#include <cuda_runtime.h>
#include <cuda_bf16.h>

#define EPS 1e-9f

static constexpr int BMAX = 1024;
static constexpr int DMAX = 512;
static constexpr int UMAX = 512;

// Scratch (device globals — no allocation allowed)
__device__ float2 g_LN[BMAX * DMAX];   // {log2|x+eps|, neg?1:0}
__device__ float  g_DW[DMAX * UMAX];   // odd(p) ? -2w : 0   (w + flag*dw = signed w)

// ---------------- Fused prepass ----------------
__global__ void prep_kernel(const float* __restrict__ x,
                            const float* __restrict__ w,
                            const float* __restrict__ p,
                            int nLN, int nDW) {
    int i = blockIdx.x * blockDim.x + threadIdx.x;
    if (i < nLN) {
        float xe = x[i] + EPS;
        g_LN[i] = make_float2(log2f(fabsf(xe)), (xe < 0.f) ? 1.f : 0.f);
    }
    if (i < nDW) {
        float pv = p[i];
        g_DW[i] = (fmodf(pv, 2.f) != 0.f) ? (-2.f * w[i]) : 0.f;
    }
}

// ---------------- Main kernel ----------------
// 256 threads, upt=1 (thread owns ONE u-col), TBT=4 b-rows.
// Grid: x = B/TBT (fastest -> consecutive blocks share u-range, L1 reuse),
//       y = U/256.
static constexpr int DC      = 8;
static constexpr int TBT     = 4;
static constexpr int THREADS = 256;

__global__ __launch_bounds__(THREADS, 4)
void power_layer_kernel(const float* __restrict__ w,
                        const float* __restrict__ p,
                        const float* __restrict__ bias,
                        float* __restrict__ out,
                        int D, int U) {
    const int u  = blockIdx.y * THREADS + threadIdx.x;
    const int b0 = blockIdx.x * TBT;

    float acc[TBT];
#pragma unroll
    for (int bb = 0; bb < TBT; bb++) acc[bb] = 0.f;

    for (int d0 = 0; d0 < D; d0 += DC) {
        // Batched independent loads (high MLP): 3*DC = 24 LDG.32
        float pr[DC], wr[DC], dwr[DC];
#pragma unroll
        for (int j = 0; j < DC; j++) {
            int r = (d0 + j) * U + u;
            pr[j]  = p[r];
            wr[j]  = w[r];
            dwr[j] = g_DW[r];
        }

#pragma unroll
        for (int bb = 0; bb < TBT; bb++) {
            // warp-uniform ln loads -> L1 broadcast; float4 = 2 x {log2, flag}
            const float4* __restrict__ ln4 =
                (const float4*)(g_LN + (size_t)(b0 + bb) * D + d0);
            float4 lnv[DC / 2];
#pragma unroll
            for (int q = 0; q < DC / 2; q++) lnv[q] = ln4[q];

#pragma unroll
            for (int j = 0; j < DC; j++) {
                const float lv = (j & 1) ? lnv[j >> 1].z : lnv[j >> 1].x;
                const float fl = (j & 1) ? lnv[j >> 1].w : lnv[j >> 1].y;

                float e = pr[j] * lv;                 // FMUL
                float v;
                asm("ex2.approx.f32 %0, %1;" : "=f"(v) : "f"(e));  // MUFU
                float ws = fmaf(fl, dwr[j], wr[j]);   // FFMA (signed weight)
                acc[bb]  = fmaf(ws, v, acc[bb]);      // FFMA
            }
        }
    }

    const float bv = bias[u];
#pragma unroll
    for (int bb = 0; bb < TBT; bb++) {
        out[(size_t)(b0 + bb) * U + u] = acc[bb] + bv;
    }
}

// ---------------- Launch ----------------
extern "C" void kernel_launch(void* const* d_in, const int* in_sizes, int n_in,
                              void* d_out, int out_size) {
    const float* x    = (const float*)d_in[0];
    const float* w    = (const float*)d_in[1];
    const float* p    = (const float*)d_in[2];
    const float* bias = (const float*)d_in[3];
    float* out        = (float*)d_out;

    const int U = in_sizes[3];            // 512
    const int D = in_sizes[1] / U;        // 512
    const int B = in_sizes[0] / D;        // 1024

    const int nLN = B * D;                // 524288
    const int nDW = D * U;                // 262144
    const int nmax = nLN > nDW ? nLN : nDW;
    prep_kernel<<<(nmax + 255) / 256, 256>>>(x, w, p, nLN, nDW);

    dim3 grid(B / TBT, U / THREADS);      // (256, 2) = 512 blocks x 8 warps
    power_layer_kernel<<<grid, THREADS>>>(w, p, bias, out, D, U);
}